// round 14
// baseline (speedup 1.0000x reference)
#include <cuda_runtime.h>
#include <cuda_fp16.h>

#define MPIF 3.14159265358979323846f

// ----------------------------------------------------------------------------
// FBP as banded GEMM on mma.sync:
//   K1 k_filter : exact closed-form ramp conv of 16 base frames -> fp16 F
//   K2 k_wbuild : per (pixel-tile tau, K-chunk ch) 64-wide banded weight rows.
//       17 chunks (circular wrap split) -> every chunk's detector span <= 53.
//   K3 k_gemm   : per (s-block, tile, n-half): D[128 s, 64 p] = sum_ch A·B^T,
//       m16n8k16 mma.sync, fp32 accum, cp.async double-buffered pipeline.
//       N=64 tiling keeps per-thread accumulators at 32 regs -> no spills
//       under the 128-reg / 2-CTA occupancy point.
// ----------------------------------------------------------------------------

static constexpr int NCH = 17;                   // K-chunks per tile

__device__ __half g_Fh[16 * 1024 * 128];         // filtered frames fp16, 4 MB
__device__ __half g_W16[128 * NCH * 128 * 64];   // weights [tau*17+ch][p][w], 34 MB
__device__ int    g_base[128 * NCH];             // band base col per (tau,ch)

// --------------------------- K1: filter -------------------------------------
__global__ __launch_bounds__(256) void k_filter(const float* __restrict__ feat) {
    __shared__ float hk[256];
    int tid = threadIdx.x;
    {
        int n = tid & 127;
        float h;
        if (n == 0) h = 0.25f;
        else if (n & 1) {
            float sv = sinpif((float)n * (1.0f / 128.0f));
            h = -1.0f / (16384.0f * sv * sv);
        } else h = 0.0f;
        hk[tid] = h * (MPIF / 128.0f);           // fold pi/A scale into filter
    }
    __syncthreads();

    int lane = tid & 31;
    int wid  = tid >> 5;
    int r = blockIdx.x * 8 + wid;                // row = t*1024 + s
    const float* row = feat + (size_t)r * 128;

    float rv[4];
    rv[0] = row[lane];      rv[1] = row[lane + 32];
    rv[2] = row[lane + 64]; rv[3] = row[lane + 96];
    float a0 = 0.f, a1 = 0.f, a2 = 0.f, a3 = 0.f;

#pragma unroll
    for (int kb = 0; kb < 4; kb++) {
        float rsel = rv[kb];
#pragma unroll
        for (int kk = 0; kk < 32; kk++) {
            float x = __shfl_sync(0xffffffffu, rsel, kk);
            int base = lane + 128 - (kb * 32 + kk);
            a0 += x * hk[base];
            a1 += x * hk[base + 32];
            a2 += x * hk[base + 64];
            a3 += x * hk[base + 96];
        }
    }
    __half* o = g_Fh + (size_t)r * 128;
    o[lane]      = __float2half_rn(a0);
    o[lane + 32] = __float2half_rn(a1);
    o[lane + 64] = __float2half_rn(a2);
    o[lane + 96] = __float2half_rn(a3);
}

// --------------------------- K2: weight build --------------------------------
__global__ __launch_bounds__(128) void k_wbuild() {
    __shared__ float sw[128 * 65];
    __shared__ float red[128];
    int bid = blockIdx.x, tau = bid / NCH, ch = bid % NCH;
    int ilo = (ch == 0)  ? 8 : 0;
    int ihi = (ch == 16) ? 8 : 16;
    int p = threadIdx.x;
    int dx = p >> 4, dy = p & 15;
    float px = (float)((tau >> 3) * 8 + dx)  - 63.5f;
    float py = (float)((tau & 7) * 16 + dy) - 63.5f;

    float umin = 1e30f;
    for (int i = ilo; i < ihi; i++) {
        int a = 8 * ch - 8 + i;                  // in [0,128), no wrap
        float th = (float)a * (1.0f / 128.0f);
        float u = px * cospif(th) + py * sinpif(th) + 63.5f;
        umin = fminf(umin, u);
    }
    red[p] = umin; __syncthreads();
    for (int o = 64; o > 0; o >>= 1) {
        if (p < o) red[p] = fminf(red[p], red[p + o]);
        __syncthreads();
    }
    int base = (int)floorf(red[0]) - 2;
    base = max(0, min(64, base)) & ~7;

    float* w64 = sw + p * 65;
    for (int k = 0; k < 64; k++) w64[k] = 0.f;
    for (int i = ilo; i < ihi; i++) {
        int a = 8 * ch - 8 + i;
        float cf = (i < 8) ? (float)i * 0.125f : 1.0f - (float)(i - 8) * 0.125f;
        float th = (float)a * (1.0f / 128.0f);
        float u = px * cospif(th) + py * sinpif(th) + 63.5f;
        float fl = floorf(u);
        int i0 = (int)fl;
        float fr = u - fl;
        int k0 = i0 - base;
        if (i0 >= 0 && i0 < 128 && k0 >= 0 && k0 < 64)
            w64[k0] += cf * (1.0f - fr);
        int i1 = i0 + 1, k1 = k0 + 1;
        if (i1 >= 0 && i1 < 128 && k1 >= 0 && k1 < 64)
            w64[k1] += cf * fr;
    }
    __half* Wp = g_W16 + (size_t)bid * 8192 + (size_t)p * 64;
#pragma unroll
    for (int k = 0; k < 64; k++) Wp[k] = __float2half_rn(w64[k]);
    if (p == 0) g_base[bid] = base;
}

// --------------------------- K3: GEMM ----------------------------------------
// grid = 2048: bid -> tau = bid>>4, sblk = (bid>>1)&7, nh = bid&1.
// 256 thr, 8 warps: mw = w&3 (32 s), nw = w>>2 in {0,1} (32 p); nt covers 4x8 p.
// Smem rows padded to 72 halves (144 B): frag LDS banks distinct; cp.async
// dst 16B-aligned.
static constexpr int SAW = 72;
static constexpr int STG = (128 + 64) * SAW;     // halves per stage (A+B)

extern __shared__ __half sm_g[];

__global__ __launch_bounds__(256, 2) void k_gemm(float* __restrict__ out) {
    int tid = threadIdx.x;
    int tau  = blockIdx.x >> 4;
    int s0   = ((blockIdx.x >> 1) & 7) * 128;
    int nh   = blockIdx.x & 1;                   // n-half: pixels nh*64..+64
    int l = tid & 31, w = tid >> 5;
    int mw = w & 3, nw = w >> 2;
    int g = l >> 2, t4 = l & 3;

    float c[2][4][4];
#pragma unroll
    for (int mt = 0; mt < 2; mt++)
#pragma unroll
        for (int nt = 0; nt < 4; nt++)
#pragma unroll
            for (int q = 0; q < 4; q++) c[mt][nt][q] = 0.f;

    // --- async chunk loader: A = F band (128 rows), B = W half (64 rows) ----
    auto issue_chunk = [&](int t, int stage) {
        int f = t & 15;                          // chunk 16 -> frame 0
        int base = g_base[tau * NCH + t];
        const uint4* Ag = (const uint4*)(g_Fh + ((size_t)f * 1024 + s0) * 128 + base);
        const uint4* Bg = (const uint4*)(g_W16 + (size_t)(tau * NCH + t) * 8192)
                          + nh * 512;            // 64 rows x 8 uint4
        __half* As = sm_g + stage * STG;
        __half* Bs = As + 128 * SAW;
#pragma unroll
        for (int k = 0; k < 6; k++) {
            int c8 = tid + 256 * k;              // 0..1535
            const uint4* src;
            __half* dst;
            if (c8 < 1024) {
                int row = c8 >> 3, j = c8 & 7;
                src = &Ag[row * 16 + j];
                dst = As + row * SAW + j * 8;
            } else {
                int r2 = c8 - 1024;              // 0..511
                int row = r2 >> 3, j = r2 & 7;
                src = &Bg[row * 8 + j];
                dst = Bs + row * SAW + j * 8;
            }
            unsigned da = (unsigned)__cvta_generic_to_shared(dst);
            asm volatile("cp.async.cg.shared.global [%0], [%1], 16;"
                         :: "r"(da), "l"(src) : "memory");
        }
        asm volatile("cp.async.commit_group;" ::: "memory");
    };

    issue_chunk(0, 0);

    for (int t = 0; t < NCH; t++) {
        if (t + 1 < NCH) {
            issue_chunk(t + 1, (t + 1) & 1);
            asm volatile("cp.async.wait_group 1;" ::: "memory");
        } else {
            asm volatile("cp.async.wait_group 0;" ::: "memory");
        }
        __syncthreads();

        const __half* As = sm_g + (t & 1) * STG;
        const __half* Bs = As + 128 * SAW;
#pragma unroll
        for (int kk = 0; kk < 64; kk += 16) {
            unsigned a[2][4];
#pragma unroll
            for (int mt = 0; mt < 2; mt++) {
                const __half* ar = &As[(mw * 32 + mt * 16 + g) * SAW + kk + t4 * 2];
                a[mt][0] = *(const unsigned*)ar;
                a[mt][1] = *(const unsigned*)(ar + 8 * SAW);
                a[mt][2] = *(const unsigned*)(ar + 8);
                a[mt][3] = *(const unsigned*)(ar + 8 * SAW + 8);
            }
#pragma unroll
            for (int nt = 0; nt < 4; nt++) {
                const __half* br = &Bs[(nw * 32 + nt * 8 + g) * SAW + kk + t4 * 2];
                unsigned b0 = *(const unsigned*)br;
                unsigned b1 = *(const unsigned*)(br + 8);
#pragma unroll
                for (int mt = 0; mt < 2; mt++) {
                    asm volatile(
                        "mma.sync.aligned.m16n8k16.row.col.f32.f16.f16.f32 "
                        "{%0,%1,%2,%3}, {%4,%5,%6,%7}, {%8,%9}, {%0,%1,%2,%3};"
                        : "+f"(c[mt][nt][0]), "+f"(c[mt][nt][1]),
                          "+f"(c[mt][nt][2]), "+f"(c[mt][nt][3])
                        : "r"(a[mt][0]), "r"(a[mt][1]),
                          "r"(a[mt][2]), "r"(a[mt][3]),
                          "r"(b0), "r"(b1));
                }
            }
        }
        __syncthreads();
    }

    // epilogue: D row = slice, cols = 2 consecutive y -> float2 stores
    int x0 = (tau >> 3) * 8, y0 = (tau & 7) * 16;
#pragma unroll
    for (int mt = 0; mt < 2; mt++) {
        int srow = s0 + mw * 32 + mt * 16 + g;
#pragma unroll
        for (int nt = 0; nt < 4; nt++) {
            int p = nh * 64 + nw * 32 + nt * 8 + t4 * 2;
            int dx = p >> 4, dy = p & 15;
            size_t off = (size_t)srow * 16384 + (size_t)(x0 + dx) * 128 + (y0 + dy);
            *(float2*)(out + off) = make_float2(c[mt][nt][0], c[mt][nt][1]);
            *(float2*)(out + off + (size_t)8 * 16384) =
                make_float2(c[mt][nt][2], c[mt][nt][3]);
        }
    }
}

// ----------------------------------------------------------------------------
extern "C" void kernel_launch(void* const* d_in, const int* in_sizes, int n_in,
                              void* d_out, int out_size) {
    (void)in_sizes; (void)n_in; (void)out_size;
    const float* feat = (const float*)d_in[0];
    float* out = (float*)d_out;

    int smem_bytes = 2 * STG * (int)sizeof(__half);      // 55296
    cudaFuncSetAttribute(k_gemm, cudaFuncAttributeMaxDynamicSharedMemorySize,
                         smem_bytes);

    k_filter<<<2048, 256>>>(feat);
    k_wbuild<<<128 * NCH, 128>>>();
    k_gemm<<<2048, 256, smem_bytes>>>(out);
}

// round 15
// speedup vs baseline: 1.1661x; 1.1661x over previous
#include <cuda_runtime.h>
#include <cuda_fp16.h>

#define MPIF 3.14159265358979323846f

// ----------------------------------------------------------------------------
// FBP as banded GEMM on mma.sync (scalar-rate HMMA fallback — measured 96% of
// the fp16 scalar pipe; tcgen05/'a'-gated PTX unavailable via compute_103):
//   K1 k_filter : ramp conv of 16 base frames -> fp16. Exploits h[even!=0]=0:
//       parity-split outputs, 64 odd taps, float2-packed h, telescoped loads.
//   K2 k_wbuild : per (tile tau, K-chunk ch) 64-wide banded weight rows,
//       17 chunks (wrap split). Angle cos/sin from a smem table (no MUFU storm).
//   K3 k_gemm   : round-13 proven config: D[128 s,128 p] = sum_ch A[s,64]*B^T,
//       m16n8k16, fp32 accum, cp.async double-buffered pipeline.
// ----------------------------------------------------------------------------

static constexpr int NCH = 17;                   // K-chunks per tile

__device__ __half g_Fh[16 * 1024 * 128];         // filtered frames fp16, 4 MB
__device__ __half g_W16[128 * NCH * 128 * 64];   // weights [tau*17+ch][p][w], 34 MB
__device__ int    g_base[128 * NCH];             // band base col per (tau,ch)

// --------------------------- K1: filter (odd-tap) ----------------------------
// F[j] = p[j]*h0 + sum_{odd n} p[j-n]*h[n]  (circular, h scaled by pi/128).
// Lane l owns outputs {2l, 2l+64} (even; odd-k sources) and {2l+1, 2l+65}
// (odd; even-k sources). h2o[m] = (h[2m+1], h[(2m+65)&127]); per-lane index
// stride 1 -> conflict-free; h2o[(l-m-1)&63] at step m is h2o[(l-m)&63] of
// step m+1 -> one fresh h-load per iteration.
__global__ __launch_bounds__(256) void k_filter(const float* __restrict__ feat) {
    __shared__ float2 h2o[64];
    __shared__ float  ps[8][128];
    int tid = threadIdx.x;
    if (tid < 64) {
        int n1 = 2 * tid + 1;
        float s1 = sinpif((float)n1 * (1.0f / 128.0f));
        int n2 = (2 * tid + 65) & 127;           // odd
        float s2 = sinpif((float)n2 * (1.0f / 128.0f));
        const float sc = -(MPIF / 128.0f) / 16384.0f;
        h2o[tid] = make_float2(sc / (s1 * s1), sc / (s2 * s2));
    }
    int l = tid & 31, w = tid >> 5;
    int r = blockIdx.x * 8 + w;                  // row = t*1024 + s
    const float* row = feat + (size_t)r * 128;
    ps[w][l]      = row[l];
    ps[w][l + 32] = row[l + 32];
    ps[w][l + 64] = row[l + 64];
    ps[w][l + 96] = row[l + 96];
    __syncthreads();

    const float h0s = 0.25f * (MPIF / 128.0f);
    float e0 = ps[w][2 * l]      * h0s;          // F[2l]
    float e1 = ps[w][2 * l + 64] * h0s;          // F[2l+64]
    float o0 = ps[w][2 * l + 1]  * h0s;          // F[2l+1]
    float o1 = ps[w][2 * l + 65] * h0s;          // F[2l+65]

    float2 hcur = h2o[l];                        // index (l-0)&63
    int idx = (l + 63) & 63;                     // (l-1)&63
#pragma unroll
    for (int m = 0; m < 64; m++) {
        float2 p2 = *(const float2*)&ps[w][2 * m];   // (p[2m], p[2m+1]) bcast
        float2 ha = h2o[idx];                        // (l-m-1)&63
        // odd outputs <- even source p[2m], h index (2(l-m)+1)
        o0 = fmaf(p2.x, hcur.x, o0);
        o1 = fmaf(p2.x, hcur.y, o1);
        // even outputs <- odd source p[2m+1], h index (2(l-m-1)+1)
        e0 = fmaf(p2.y, ha.x, e0);
        e1 = fmaf(p2.y, ha.y, e1);
        hcur = ha;
        idx = (idx + 63) & 63;
    }

    __half* o = g_Fh + (size_t)r * 128;
    __half2 lo = __floats2half2_rn(e0, o0);      // F[2l], F[2l+1]
    __half2 hi = __floats2half2_rn(e1, o1);      // F[2l+64], F[2l+65]
    *(__half2*)(o + 2 * l)      = lo;
    *(__half2*)(o + 2 * l + 64) = hi;
}

// --------------------------- K2: weight build --------------------------------
__global__ __launch_bounds__(128) void k_wbuild() {
    __shared__ float sw[128 * 65];
    __shared__ float red[128];
    __shared__ float2 csang[16];                 // (cos, sin) per chunk angle
    int bid = blockIdx.x, tau = bid / NCH, ch = bid % NCH;
    int ilo = (ch == 0)  ? 8 : 0;
    int ihi = (ch == 16) ? 8 : 16;
    int p = threadIdx.x;
    if (p < 16) {
        int a = 8 * ch - 8 + p;
        float th = (float)a * (1.0f / 128.0f);
        csang[p] = make_float2(cospif(th), sinpif(th));
    }
    __syncthreads();

    int dx = p >> 4, dy = p & 15;
    float px = (float)((tau >> 3) * 8 + dx)  - 63.5f;
    float py = (float)((tau & 7) * 16 + dy) - 63.5f;

    float umin = 1e30f;
    for (int i = ilo; i < ihi; i++) {
        float2 cs = csang[i];
        float u = px * cs.x + py * cs.y + 63.5f;
        umin = fminf(umin, u);
    }
    red[p] = umin; __syncthreads();
    for (int o = 64; o > 0; o >>= 1) {
        if (p < o) red[p] = fminf(red[p], red[p + o]);
        __syncthreads();
    }
    int base = (int)floorf(red[0]) - 2;
    base = max(0, min(64, base)) & ~7;

    float* w64 = sw + p * 65;
    for (int k = 0; k < 64; k++) w64[k] = 0.f;
    for (int i = ilo; i < ihi; i++) {
        float cf = (i < 8) ? (float)i * 0.125f : 1.0f - (float)(i - 8) * 0.125f;
        float2 cs = csang[i];
        float u = px * cs.x + py * cs.y + 63.5f;
        float fl = floorf(u);
        int i0 = (int)fl;
        float fr = u - fl;
        int k0 = i0 - base;
        if (i0 >= 0 && i0 < 128 && k0 >= 0 && k0 < 64)
            w64[k0] += cf * (1.0f - fr);
        int i1 = i0 + 1, k1 = k0 + 1;
        if (i1 >= 0 && i1 < 128 && k1 >= 0 && k1 < 64)
            w64[k1] += cf * fr;
    }
    __half* Wp = g_W16 + (size_t)bid * 8192 + (size_t)p * 64;
#pragma unroll
    for (int k = 0; k < 64; k++) Wp[k] = __float2half_rn(w64[k]);
    if (p == 0) g_base[bid] = base;
}

// --------------------------- K3: GEMM (round-13 proven) ----------------------
static constexpr int SAW = 72;
static constexpr int STG = 2 * 128 * SAW;        // halves per stage (A+B)

extern __shared__ __half sm_g[];

__global__ __launch_bounds__(256, 2) void k_gemm(float* __restrict__ out) {
    int tid = threadIdx.x;
    int tau = blockIdx.x >> 3;
    int s0  = (blockIdx.x & 7) * 128;
    int l = tid & 31, w = tid >> 5;
    int mw = w & 3, nw = w >> 2;
    int g = l >> 2, t4 = l & 3;

    float c[2][8][4];
#pragma unroll
    for (int mt = 0; mt < 2; mt++)
#pragma unroll
        for (int nt = 0; nt < 8; nt++)
#pragma unroll
            for (int q = 0; q < 4; q++) c[mt][nt][q] = 0.f;

    auto issue_chunk = [&](int t, int stage) {
        int f = t & 15;                          // chunk 16 -> frame 0
        int base = g_base[tau * NCH + t];
        const uint4* Ag = (const uint4*)(g_Fh + ((size_t)f * 1024 + s0) * 128 + base);
        const uint4* Bg = (const uint4*)(g_W16 + (size_t)(tau * NCH + t) * 8192);
        __half* As = sm_g + stage * STG;
        __half* Bs = As + 128 * SAW;
#pragma unroll
        for (int k = 0; k < 8; k++) {
            int c8 = tid + 256 * k;
            int row = (c8 >> 3) & 127;
            int j = c8 & 7;
            const uint4* src = (c8 < 1024) ? &Ag[row * 16 + j] : &Bg[row * 8 + j];
            __half* dst = ((c8 < 1024) ? As : Bs) + row * SAW + j * 8;
            unsigned da = (unsigned)__cvta_generic_to_shared(dst);
            asm volatile("cp.async.cg.shared.global [%0], [%1], 16;"
                         :: "r"(da), "l"(src) : "memory");
        }
        asm volatile("cp.async.commit_group;" ::: "memory");
    };

    issue_chunk(0, 0);

    for (int t = 0; t < NCH; t++) {
        if (t + 1 < NCH) {
            issue_chunk(t + 1, (t + 1) & 1);
            asm volatile("cp.async.wait_group 1;" ::: "memory");
        } else {
            asm volatile("cp.async.wait_group 0;" ::: "memory");
        }
        __syncthreads();

        const __half* As = sm_g + (t & 1) * STG;
        const __half* Bs = As + 128 * SAW;
#pragma unroll
        for (int kk = 0; kk < 64; kk += 16) {
            unsigned a[2][4];
#pragma unroll
            for (int mt = 0; mt < 2; mt++) {
                const __half* ar = &As[(mw * 32 + mt * 16 + g) * SAW + kk + t4 * 2];
                a[mt][0] = *(const unsigned*)ar;
                a[mt][1] = *(const unsigned*)(ar + 8 * SAW);
                a[mt][2] = *(const unsigned*)(ar + 8);
                a[mt][3] = *(const unsigned*)(ar + 8 * SAW + 8);
            }
#pragma unroll
            for (int nt = 0; nt < 8; nt++) {
                const __half* br = &Bs[(nw * 64 + nt * 8 + g) * SAW + kk + t4 * 2];
                unsigned b0 = *(const unsigned*)br;
                unsigned b1 = *(const unsigned*)(br + 8);
#pragma unroll
                for (int mt = 0; mt < 2; mt++) {
                    asm volatile(
                        "mma.sync.aligned.m16n8k16.row.col.f32.f16.f16.f32 "
                        "{%0,%1,%2,%3}, {%4,%5,%6,%7}, {%8,%9}, {%0,%1,%2,%3};"
                        : "+f"(c[mt][nt][0]), "+f"(c[mt][nt][1]),
                          "+f"(c[mt][nt][2]), "+f"(c[mt][nt][3])
                        : "r"(a[mt][0]), "r"(a[mt][1]),
                          "r"(a[mt][2]), "r"(a[mt][3]),
                          "r"(b0), "r"(b1));
                }
            }
        }
        __syncthreads();
    }

    int x0 = (tau >> 3) * 8, y0 = (tau & 7) * 16;
#pragma unroll
    for (int mt = 0; mt < 2; mt++) {
        int srow = s0 + mw * 32 + mt * 16 + g;
#pragma unroll
        for (int nt = 0; nt < 8; nt++) {
            int p = nw * 64 + nt * 8 + t4 * 2;
            int dx = p >> 4, dy = p & 15;
            size_t off = (size_t)srow * 16384 + (size_t)(x0 + dx) * 128 + (y0 + dy);
            *(float2*)(out + off) = make_float2(c[mt][nt][0], c[mt][nt][1]);
            *(float2*)(out + off + (size_t)8 * 16384) =
                make_float2(c[mt][nt][2], c[mt][nt][3]);
        }
    }
}

// ----------------------------------------------------------------------------
extern "C" void kernel_launch(void* const* d_in, const int* in_sizes, int n_in,
                              void* d_out, int out_size) {
    (void)in_sizes; (void)n_in; (void)out_size;
    const float* feat = (const float*)d_in[0];
    float* out = (float*)d_out;

    int smem_bytes = 2 * STG * (int)sizeof(__half);      // 73728
    cudaFuncSetAttribute(k_gemm, cudaFuncAttributeMaxDynamicSharedMemorySize,
                         smem_bytes);

    k_filter<<<2048, 256>>>(feat);
    k_wbuild<<<128 * NCH, 128>>>();
    k_gemm<<<1024, 256, smem_bytes>>>(out);
}